// round 15
// baseline (speedup 1.0000x reference)
#include <cuda_runtime.h>
#include <cuda_fp16.h>
#include <math.h>

// ---------------- problem constants ----------------
#define NANCH   120000
#define KPRE    2000
#define KPOST   512
#define IMG     800.0f
#define SCALE   0.25f
#define CLIPC   4.135166556742356f
#define HF      200
#define WF      200
#define CF      256
#define HW      (HF*WF)          // 40000
#define NWORD   32
#define NPAD    2048
#define PT      625              // 64-wide p tiles
#define TTOT    (PT*4)           // 2500 transpose tiles
#define NTRI    528              // upper-tri 64x64 IoU tiles
#define NIOU    (NTRI/4)         // 132
#define MAXKEY  2560
#define NRANKB  160              // rank blocks: 16 candidates/block * 160 = 2560

// ---------------- device scratch (all .bss zero at process start) ----------------
__device__ unsigned int        g_hist[65536];
__device__ unsigned int        g_hist2[65536];
__device__ int                 g_T16;
__device__ unsigned int        g_S;
__device__ int                 g_cnt1, g_cnt2;
__device__ unsigned int        g_ctrd, g_ctrg, g_ctri, g_rankdone, g_thrflag;
__device__ unsigned long long  g_cand[2048];
__device__ unsigned long long  g_cand2[4096];
__device__ unsigned long long  g_keys[MAXKEY];
__device__ int                 g_M;
__device__ float4              g_cand_boxes[NPAD];
__device__ unsigned long long  g_mask[NPAD * NWORD];   // lower-tri never written (stays 0)
__device__ float4              g_fboxes[KPOST];
__device__ int                 g_valid[KPOST];
__device__ __align__(16) __half g_featT[HW * CF];      // (H*W, C) fp16, ~20.5 MB

// ---------------- helpers ----------------
__device__ __forceinline__ unsigned flipf(float v) {
    unsigned u = __float_as_uint(v);
    return (u & 0x80000000u) ? ~u : (u | 0x80000000u);
}

// ---------------- K1: front = transpose everywhere; hist/gather woven into blocks 0..nbH-1 ----------------
union FrontShared {
    float tile[64][65];                  // 16.6 KB (transpose)
    struct {
        unsigned csum[256];
        unsigned sbin[256];
        int      schunk;
        unsigned sbase;
        unsigned sT32;
        int      kc;
    } h;
};

__global__ void __launch_bounds__(256, 8)
front_kernel(const float* __restrict__ f,
             const float* __restrict__ obj, int N, int nbH) {
    __shared__ FrontShared u;
    int tid = threadIdx.x;
    int blk = blockIdx.x;
    bool hybrid = (blk < nbH);

    // ---- phase 0 (hybrid only): histogram + non-blocking barrier arrive ----
    int i = blk * 256 + tid;
    unsigned uv = 0u;
    if (hybrid) {
        if (i < N) {
            uv = flipf(obj[i]);
            atomicAdd(&g_hist[uv >> 16], 1u);
        }
        __syncthreads();
        if (tid == 0) { __threadfence(); atomicAdd(&g_ctrd, 1u); }
    }

    // ---- phase 1 (all blocks): fp16 transpose of tile `blk` ----
    {
        int pb = blk % PT, cb = blk / PT;
        int p0 = pb * 64, c0 = cb * 64;
        #pragma unroll
        for (int r = 0; r < 4; r++) {
            int slot = r * 256 + tid;
            int ty = slot >> 4, tx = slot & 15;
            float4 v = *(const float4*)&f[(size_t)(c0 + ty) * HW + p0 + 4 * tx];
            u.tile[ty][4 * tx + 0] = v.x;
            u.tile[ty][4 * tx + 1] = v.y;
            u.tile[ty][4 * tx + 2] = v.z;
            u.tile[ty][4 * tx + 3] = v.w;
        }
        __syncthreads();
        #pragma unroll
        for (int r = 0; r < 4; r++) {
            int slot = r * 256 + tid;
            int pp = slot >> 4, k = slot & 15;
            __half2 h0 = __floats2half2_rn(u.tile[4 * k + 0][pp], u.tile[4 * k + 1][pp]);
            __half2 h1 = __floats2half2_rn(u.tile[4 * k + 2][pp], u.tile[4 * k + 3][pp]);
            uint2 pk;
            pk.x = *(unsigned*)&h0;
            pk.y = *(unsigned*)&h1;
            *(uint2*)&g_featT[(size_t)(p0 + pp) * CF + c0 + 4 * k] = pk;
        }
    }
    if (!hybrid) return;
    __syncthreads();     // tile smem dead; h struct may now be used

    // ---- phase 2: threshold (block 0) / wait (others) ----
    int w0 = tid >> 5, l = tid & 31;
    if (blk == 0) {
        if (tid == 0) {
            while (*(volatile unsigned*)&g_ctrd < (unsigned)nbH) {}
            __threadfence();
        }
        __syncthreads();
        for (int t = w0; t < 256; t += 8) {
            unsigned s = 0;
            for (int b = l; b < 256; b += 32) s += g_hist[t * 256 + b];
            #pragma unroll
            for (int o = 16; o; o >>= 1) s += __shfl_down_sync(0xffffffffu, s, o);
            if (!l) u.h.csum[t] = s;
        }
        __syncthreads();
        if (tid == 0) {
            unsigned run = 0; int ch = 255; unsigned bs = 0;
            for (int t = 255; t >= 0; t--) {
                if (run + u.h.csum[t] >= KPRE) { ch = t; bs = run; break; }
                run += u.h.csum[t];
            }
            u.h.schunk = ch; u.h.sbase = bs;
        }
        __syncthreads();
        int ch = u.h.schunk;
        if (w0 == 0) for (int b = l; b < 256; b += 32) u.h.sbin[b] = g_hist[ch * 256 + b];
        __syncthreads();
        if (tid == 0) {
            unsigned cum = u.h.sbase;
            for (int b = 255; b >= 0; b--) {
                if (cum + u.h.sbin[b] >= KPRE) { g_T16 = ch * 256 + b; g_S = cum; break; }
                cum += u.h.sbin[b];
            }
            __threadfence();
            atomicExch(&g_thrflag, 1u);
        }
        __syncthreads();
    } else {
        if (tid == 0) {
            while (*(volatile unsigned*)&g_thrflag == 0u) {}
            __threadfence();
        }
        __syncthreads();
    }

    // ---- phase 3: gather ----
    if (i < N) {
        int hi = (int)(uv >> 16);
        int T = g_T16;
        if (hi > T) {
            int p = atomicAdd(&g_cnt1, 1);
            if (p < 2048)
                g_cand[p] = ((unsigned long long)uv << 32) |
                            (unsigned long long)(0xFFFFFFFFu - (unsigned)i);
        } else if (hi == T) {
            int p = atomicAdd(&g_cnt2, 1);
            if (p < 4096)
                g_cand2[p] = ((unsigned long long)uv << 32) |
                             (unsigned long long)(0xFFFFFFFFu - (unsigned)i);
            atomicAdd(&g_hist2[uv & 0xFFFFu], 1u);
        }
    }
    __syncthreads();
    __shared__ int lastg;
    if (tid == 0) {
        __threadfence();
        lastg = (atomicAdd(&g_ctrg, 1u) == (unsigned)(nbH - 1));
    }
    __syncthreads();
    if (!lastg) return;

    // ---- phase 4 (last gather block): 32-bit refine + compact key list ----
    for (int t = w0; t < 256; t += 8) {
        unsigned s = 0;
        for (int b = l; b < 256; b += 32) s += g_hist2[t * 256 + b];
        #pragma unroll
        for (int o = 16; o; o >>= 1) s += __shfl_down_sync(0xffffffffu, s, o);
        if (!l) u.h.csum[t] = s;
    }
    __syncthreads();
    unsigned need = KPRE - g_S;
    if (tid == 0) {
        unsigned run = 0; int ch = 0; unsigned bs = 0;
        for (int t = 255; t >= 0; t--) {
            if (run + u.h.csum[t] >= need) { ch = t; bs = run; break; }
            run += u.h.csum[t];
        }
        u.h.schunk = ch; u.h.sbase = bs;
    }
    __syncthreads();
    int ch = u.h.schunk;
    if (w0 == 0) for (int b = l; b < 256; b += 32) u.h.sbin[b] = g_hist2[ch * 256 + b];
    __syncthreads();
    if (tid == 0) {
        unsigned cum = u.h.sbase;
        for (int b = 255; b >= 0; b--) {
            if (cum + u.h.sbin[b] >= need) {
                u.h.sT32 = ((unsigned)g_T16 << 16) | (unsigned)(ch * 256 + b);
                break;
            }
            cum += u.h.sbin[b];
        }
        u.h.kc = 0;
    }
    __syncthreads();
    unsigned T32 = u.h.sT32;
    int n1 = g_cnt1; if (n1 > 2048) n1 = 2048;
    for (int k = tid; k < n1; k += 256) g_keys[k] = g_cand[k];
    if (tid == 0) u.h.kc = n1;
    __syncthreads();
    int n2 = g_cnt2; if (n2 > 4096) n2 = 4096;
    for (int k = tid; k < n2; k += 256) {
        unsigned long long key = g_cand2[k];
        if ((unsigned)(key >> 32) >= T32) {
            int p = atomicAdd(&u.h.kc, 1);
            if (p < MAXKEY) g_keys[p] = key;
        }
    }
    __syncthreads();
    if (tid == 0) g_M = (u.h.kc < MAXKEY) ? u.h.kc : MAXKEY;
}

// ---------------- K2: mid = rank-v2 (blocks 0..159) | iou (160.., spin) + last-block NMS ----------------
union MidShared {
    unsigned long long sk[MAXKEY];       // 20 KB (rank branch)
    struct {
        float4 cb[4][64];                //  4 KB
        float  cA[4][64];                //  1 KB
        unsigned long long buf[2][64][33];   // 33.8 KB
        unsigned long long skeep[NWORD];
        unsigned long long part_sm[8];
        unsigned long long keptw;
    } iou;                               // ~39 KB
};

__global__ void mid_kernel(const float4* __restrict__ anchors,
                           const float4* __restrict__ deltas) {
    __shared__ MidShared u;
    __shared__ int s_stop;
    int tid = threadIdx.x;

    if (blockIdx.x < NRANKB) {
        // ======== rank v2: 16 threads per candidate ========
        int M = g_M;
        for (int j = tid; j < MAXKEY; j += 256)
            u.sk[j] = (j < M) ? g_keys[j] : 0ull;
        __syncthreads();
        int z = blockIdx.x * 256 + tid;
        if (z >= KPRE && z < NPAD) g_cand_boxes[z] = make_float4(0.f, 0.f, 0.f, 0.f);

        int cand = blockIdx.x * 16 + (tid >> 4);   // 0..2559
        int part = tid & 15;
        if (cand < M) {
            unsigned long long key = u.sk[cand];
            const ulonglong2* sk2 = (const ulonglong2*)u.sk;
            int rank = 0;
            #pragma unroll 8
            for (int j = part; j < MAXKEY / 2; j += 16) {
                ulonglong2 v = sk2[j];
                rank += (v.x > key);
                rank += (v.y > key);
            }
            #pragma unroll
            for (int o = 8; o; o >>= 1)
                rank += __shfl_down_sync(0xffffffffu, rank, o, 16);
            if (part == 0 && rank < KPRE) {
                unsigned i = ~(unsigned)(key & 0xFFFFFFFFull);
                float4 a = anchors[i];
                float4 d = deltas[i];
                float w  = a.z - a.x, h = a.w - a.y;
                float cx = a.x + 0.5f * w, cy = a.y + 0.5f * h;
                float dw = fminf(d.z, CLIPC), dh = fminf(d.w, CLIPC);
                float pcx = d.x * w + cx, pcy = d.y * h + cy;
                float pw  = expf(dw) * w, ph = expf(dh) * h;
                float bx1 = fminf(fmaxf(pcx - 0.5f * pw, 0.f), IMG);
                float by1 = fminf(fmaxf(pcy - 0.5f * ph, 0.f), IMG);
                float bx2 = fminf(fmaxf(pcx + 0.5f * pw, 0.f), IMG);
                float by2 = fminf(fmaxf(pcy + 0.5f * ph, 0.f), IMG);
                g_cand_boxes[rank] = make_float4(bx1, by1, bx2, by2);
            }
        }
        __syncthreads();
        if (tid == 0) { __threadfence(); atomicAdd(&g_rankdone, 1u); }
        return;
    }

    // ======== iou blocks: wait for rank, then 4 upper-tri tiles ========
    if (tid == 0) {
        while (*(volatile unsigned*)&g_rankdone < NRANKB) {}
        __threadfence();
    }
    __syncthreads();

    int sub = tid >> 6, tx = tid & 63;
    int t = (blockIdx.x - NRANKB) * 4 + sub;   // 0..527
    int ib = 0, off = 0;
    for (int r = 0; r < 32; r++) {
        int cnt = 32 - r;
        if (t < off + cnt) { ib = r; break; }
        off += cnt;
    }
    int by = ib + (t - off);

    float4 bb = g_cand_boxes[by * 64 + tx];
    u.iou.cb[sub][tx] = bb;
    u.iou.cA[sub][tx] = 0.7f * (bb.z - bb.x) * (bb.w - bb.y);
    __syncthreads();

    int i = ib * 64 + tx;
    float4 a = g_cand_boxes[i];
    float c0 = 0.7f * ((a.z - a.x) * (a.w - a.y) + 1e-6f);
    unsigned long long bits = 0ull;
    #pragma unroll 8
    for (int jj = 0; jj < 64; jj++) {
        float4 b = u.iou.cb[sub][jj];
        float lx = fmaxf(a.x, b.x), ly = fmaxf(a.y, b.y);
        float rx = fminf(a.z, b.z), ry = fminf(a.w, b.w);
        float wx = fmaxf(rx - lx, 0.f), wy = fmaxf(ry - ly, 0.f);
        float inter = wx * wy;
        unsigned long long p = (fmaf(1.7f, inter, -(c0 + u.iou.cA[sub][jj])) > 0.f);
        bits |= p << jj;
    }
    if (by == ib) bits &= (tx == 63) ? 0ull : (~0ull << (tx + 1));
    g_mask[(size_t)i * NWORD + by] = bits;

    __syncthreads();
    __shared__ int lastf;
    if (tid == 0) {
        __threadfence();
        lastf = (atomicAdd(&g_ctri, 1u) == NIOU - 1);
    }
    __syncthreads();
    if (!lastf) return;

    // ======== parallel NMS (cluster-skip greedy + distributed accumulation) ========
    int lane = tid & 31;
    int wrp  = tid >> 5;
    unsigned long long part_reg = 0ull;
    if (tid == 0) s_stop = 0;
    if (tid < 8) u.iou.part_sm[tid] = 0ull;
    #pragma unroll
    for (int k = 0; k < 8; k++) {
        int idx = tid + k * 256;
        u.iou.buf[0][idx >> 5][idx & 31] = g_mask[(size_t)(idx >> 5) * NWORD + (idx & 31)];
    }
    __syncthreads();

    int kept_total = 0;
    int cend = NWORD;
    for (int c = 0; c < NWORD; c++) {
        int par = c & 1;
        if (c + 1 < NWORD) {
            int base1 = (c + 1) * 64;
            #pragma unroll
            for (int k = 0; k < 8; k++) {
                int idx = tid + k * 256;
                u.iou.buf[par ^ 1][idx >> 5][idx & 31] =
                    g_mask[(size_t)(base1 + (idx >> 5)) * NWORD + (idx & 31)];
            }
        }
        if (wrp == 0) {
            unsigned long long rem = (lane < 8) ? u.iou.part_sm[lane] : 0ull;
            rem |= __shfl_xor_sync(0xffffffffu, rem, 4);
            rem |= __shfl_xor_sync(0xffffffffu, rem, 2);
            rem |= __shfl_xor_sync(0xffffffffu, rem, 1);
            rem  = __shfl_sync(0xffffffffu, rem, 0);
            unsigned long long keepmask = (c == NWORD - 1) ? 0xFFFFull : ~0ull;
            unsigned long long td = ~rem & keepmask;
            unsigned long long sd_lo = u.iou.buf[par][lane][c];
            unsigned long long sd_hi = u.iou.buf[par][lane + 32][c];
            unsigned long long kept = 0ull;
            while (td) {
                unsigned long long row = 0ull;
                if ((td >> lane) & 1ull)        row  = sd_lo;
                if ((td >> (lane + 32)) & 1ull) row |= sd_hi;
                #pragma unroll
                for (int o = 16; o; o >>= 1)
                    row |= __shfl_xor_sync(0xffffffffu, row, o);
                unsigned long long tgt = row & td;
                if (tgt == 0ull) { kept |= td; break; }
                int s = __ffsll((long long)tgt) - 1;
                unsigned long long low = td & ((1ull << s) - 1ull);
                kept |= low;
                unsigned long long row2 = 0ull;
                if ((low >> lane) & 1ull)        row2  = sd_lo;
                if ((low >> (lane + 32)) & 1ull) row2 |= sd_hi;
                #pragma unroll
                for (int o = 16; o; o >>= 1)
                    row2 |= __shfl_xor_sync(0xffffffffu, row2, o);
                td &= ~(low | row2);
            }
            if (lane == 0) {
                u.iou.skeep[c] = kept;
                u.iou.keptw    = kept;
                kept_total += __popcll(kept);
                if (kept_total >= KPOST) s_stop = 1;
            }
        }
        __syncthreads();
        if (s_stop) { cend = c + 1; break; }
        unsigned long long kw = u.iou.keptw;
        int cnt2 = 0;
        while (kw) {
            int b = __ffsll((long long)kw) - 1;
            if ((cnt2 & 7) == wrp) part_reg |= u.iou.buf[par][b][lane];
            kw &= (kw - 1);
            cnt2++;
        }
        if (lane == c + 1) u.iou.part_sm[wrp] = part_reg;
        __syncthreads();
    }

    // ---- compaction (warp 0) ----
    if (wrp != 0) return;
    for (int cc = cend + lane; cc < NWORD; cc += 32) u.iou.skeep[cc] = 0ull;
    __syncwarp();
    for (int s = lane; s < KPOST; s += 32) g_valid[s] = 0;
    __syncwarp();
    unsigned long long kw = u.iou.skeep[lane];
    int cnt = __popcll(kw);
    int pre = cnt;
    #pragma unroll
    for (int o = 1; o < 32; o <<= 1) {
        int n = __shfl_up_sync(0xffffffffu, pre, o);
        if (lane >= o) pre += n;
    }
    pre -= cnt;
    unsigned long long w2 = kw; int r = 0;
    while (w2) {
        int b = __ffsll((long long)w2) - 1;
        int s = pre + r;
        if (s < KPOST) {
            g_valid[s] = 1;
            g_fboxes[s] = g_cand_boxes[lane * 64 + b];
        }
        w2 &= (w2 - 1); r++;
    }
}

// ---------------- K3: ROIAlign + self-clean for next graph replay ----------------
#define SPAD   65
#define SOUT_F 3188                             // 49*65=3185, padded (16B align)
#define ROI_SMEM (SOUT_F*4 + 196*16 + 196*16)   // ~19.0 KB

__global__ void __launch_bounds__(256, 8)
roi_kernel(float* __restrict__ out) {
    extern __shared__ float sm[];
    float*  s_out = sm;
    int4*   s_off = (int4*)(sm + SOUT_F);
    float4* s_w   = (float4*)(s_off + 196);

    int slot = blockIdx.x >> 2;
    int quar = blockIdx.x & 3;
    int tid  = threadIdx.x;
    float* o = out + (size_t)slot * (CF * 49) + quar * (64 * 49);

    // ---- self-clean scratch for the NEXT replay ----
    if (tid < 16) {
        int idx = blockIdx.x * 16 + tid;        // 2048*16 = 32768 uint4 exactly
        uint4 z = make_uint4(0, 0, 0, 0);
        if (idx < 16384) ((uint4*)g_hist)[idx] = z;
        else             ((uint4*)g_hist2)[idx - 16384] = z;
    }
    if (blockIdx.x == 0 && tid == 0) {
        g_cnt1 = 0; g_cnt2 = 0; g_ctrd = 0; g_ctrg = 0; g_ctri = 0;
        g_rankdone = 0; g_thrflag = 0;
    }

    if (!g_valid[slot]) {
        for (int g = tid; g < 64 * 49; g += 256) o[g] = 0.0f;
        return;
    }
    float4 b = g_fboxes[slot];
    if (tid < 196) {
        float x1 = b.x * SCALE, y1 = b.y * SCALE;
        float x2 = b.z * SCALE, y2 = b.w * SCALE;
        float rw = fmaxf(x2 - x1, 1.0f), rh = fmaxf(y2 - y1, 1.0f);
        int sy = tid / 14, sx = tid % 14;
        float yv = y1 + ((float)sy + 0.5f) * (rh / 14.0f);
        float xv = x1 + ((float)sx + 0.5f) * (rw / 14.0f);
        yv = fminf(fmaxf(yv, 0.0f), (float)(HF - 1));
        xv = fminf(fmaxf(xv, 0.0f), (float)(WF - 1));
        int y0 = (int)floorf(yv), x0 = (int)floorf(xv);
        int y1i = min(y0 + 1, HF - 1), x1i = min(x0 + 1, WF - 1);
        float ly = yv - (float)y0, lx = xv - (float)x0;
        s_off[tid] = make_int4((y0 * WF + x0) * CF,  (y0 * WF + x1i) * CF,
                               (y1i * WF + x0) * CF, (y1i * WF + x1i) * CF);
        s_w[tid] = make_float4((1.f - ly) * (1.f - lx), (1.f - ly) * lx,
                               ly * (1.f - lx),          ly * lx);
    }
    __syncthreads();

    int cg = tid & 15;
    int pq = tid >> 4;
    int cbase = quar * 64 + 4 * cg;

    for (int p = pq; p < 49; p += 16) {
        int oy = p / 7, ox = p % 7;
        float ax = 0.f, ay = 0.f, az = 0.f, aw = 0.f;
        #pragma unroll
        for (int a = 0; a < 2; a++) {
            #pragma unroll
            for (int bbq = 0; bbq < 2; bbq++) {
                int s = (2 * oy + a) * 14 + (2 * ox + bbq);
                int4   of = s_off[s];
                float4 wv = s_w[s];
                uint2 r00 = *(const uint2*)&g_featT[(size_t)(unsigned)of.x + cbase];
                uint2 r01 = *(const uint2*)&g_featT[(size_t)(unsigned)of.y + cbase];
                uint2 r10 = *(const uint2*)&g_featT[(size_t)(unsigned)of.z + cbase];
                uint2 r11 = *(const uint2*)&g_featT[(size_t)(unsigned)of.w + cbase];
                float2 a0 = __half22float2(*(__half2*)&r00.x);
                float2 a1 = __half22float2(*(__half2*)&r00.y);
                float2 b0 = __half22float2(*(__half2*)&r01.x);
                float2 b1 = __half22float2(*(__half2*)&r01.y);
                float2 c0 = __half22float2(*(__half2*)&r10.x);
                float2 c1 = __half22float2(*(__half2*)&r10.y);
                float2 d0 = __half22float2(*(__half2*)&r11.x);
                float2 d1 = __half22float2(*(__half2*)&r11.y);
                ax += wv.x * a0.x + wv.y * b0.x + wv.z * c0.x + wv.w * d0.x;
                ay += wv.x * a0.y + wv.y * b0.y + wv.z * c0.y + wv.w * d0.y;
                az += wv.x * a1.x + wv.y * b1.x + wv.z * c1.x + wv.w * d1.x;
                aw += wv.x * a1.y + wv.y * b1.y + wv.z * c1.y + wv.w * d1.y;
            }
        }
        int base = p * SPAD + 4 * cg;
        s_out[base + 0] = ax * 0.25f;
        s_out[base + 1] = ay * 0.25f;
        s_out[base + 2] = az * 0.25f;
        s_out[base + 3] = aw * 0.25f;
    }
    __syncthreads();

    for (int g = tid; g < 64 * 49; g += 256) {
        int cc = g / 49;
        int p  = g - 49 * cc;
        o[g] = s_out[p * SPAD + cc];
    }
}

// ---------------- launcher ----------------
extern "C" void kernel_launch(void* const* d_in, const int* in_sizes, int n_in,
                              void* d_out, int out_size) {
    const float*  feature = (const float*)d_in[0];
    const float*  obj     = (const float*)d_in[1];
    const float4* deltas  = (const float4*)d_in[2];
    const float4* anchors = (const float4*)d_in[3];
    float* out = (float*)d_out;
    int N = in_sizes[1];
    int nbH = (N + 255) / 256;   // 469 <= TTOT

    cudaFuncSetAttribute(roi_kernel, cudaFuncAttributeMaxDynamicSharedMemorySize, ROI_SMEM);

    front_kernel<<<TTOT, 256>>>(feature, obj, N, nbH);
    mid_kernel<<<NRANKB + NIOU, 256>>>(anchors, deltas);
    roi_kernel<<<4 * KPOST, 256, ROI_SMEM>>>(out);
}

// round 16
// speedup vs baseline: 1.0654x; 1.0654x over previous
#include <cuda_runtime.h>
#include <cuda_fp16.h>
#include <math.h>

// ---------------- problem constants ----------------
#define NANCH   120000
#define KPRE    2000
#define KPOST   512
#define IMG     800.0f
#define SCALE   0.25f
#define CLIPC   4.135166556742356f
#define HF      200
#define WF      200
#define CF      256
#define HW      (HF*WF)          // 40000
#define NWORD   32
#define NPAD    2048
#define PT      625              // 64-wide p tiles
#define TTOT    (PT*4)           // 2500 transpose tiles
#define NTRI    528              // upper-tri 64x64 IoU tiles
#define NIOU    (NTRI/4)         // 132
#define MAXKEY  2560
#define NRANKB  160              // rank blocks: 16 candidates/block * 160 = 2560

// ---------------- device scratch (all .bss zero at process start; self-cleaned by roi) ----------------
__device__ unsigned int        g_hist[65536];
__device__ unsigned int        g_hist2[65536];
__device__ int                 g_T16;
__device__ unsigned int        g_S;
__device__ int                 g_cnt1, g_cnt2;
__device__ unsigned int        g_ctrd, g_ctrg, g_ctri, g_rankdone;
__device__ unsigned long long  g_cand[2048];
__device__ unsigned long long  g_cand2[4096];
__device__ unsigned long long  g_keys[MAXKEY];
__device__ int                 g_M;
__device__ float4              g_cand_boxes[NPAD];
__device__ unsigned long long  g_mask[NPAD * NWORD];   // lower-tri never written (stays 0)
__device__ float4              g_fboxes[KPOST];
__device__ int                 g_valid[KPOST];
__device__ __align__(16) __half g_featT[HW * CF];      // (H*W, C) fp16, ~20.5 MB

// ---------------- helpers ----------------
__device__ __forceinline__ unsigned flipf(float v) {
    unsigned u = __float_as_uint(v);
    return (u & 0x80000000u) ? ~u : (u | 0x80000000u);
}

// ---------------- K1: objectness histogram + (last block) coalesced 16-bit threshold ----------------
__global__ void hist_kernel(const float* __restrict__ obj, int N) {
    int i = blockIdx.x * 256 + threadIdx.x;
    if (i < N) atomicAdd(&g_hist[flipf(obj[i]) >> 16], 1u);
    __syncthreads();
    __shared__ int lastf;
    if (threadIdx.x == 0) {
        __threadfence();
        lastf = (atomicAdd(&g_ctrd, 1u) == gridDim.x - 1);
    }
    __syncthreads();
    if (!lastf) return;

    __shared__ unsigned csum[256];
    __shared__ unsigned sbin[256];
    __shared__ int schunk;
    __shared__ unsigned sbase;
    int tid = threadIdx.x, w0 = tid >> 5, l = tid & 31;
    for (int t = w0; t < 256; t += 8) {
        unsigned s = 0;
        for (int b = l; b < 256; b += 32) s += g_hist[t * 256 + b];
        #pragma unroll
        for (int o = 16; o; o >>= 1) s += __shfl_down_sync(0xffffffffu, s, o);
        if (!l) csum[t] = s;
    }
    __syncthreads();
    if (tid == 0) {
        unsigned run = 0; int ch = 255; unsigned bs = 0;
        for (int t = 255; t >= 0; t--) {
            if (run + csum[t] >= KPRE) { ch = t; bs = run; break; }
            run += csum[t];
        }
        schunk = ch; sbase = bs;
    }
    __syncthreads();
    int ch = schunk;
    if (w0 == 0) for (int b = l; b < 256; b += 32) sbin[b] = g_hist[ch * 256 + b];
    __syncthreads();
    if (tid == 0) {
        unsigned cum = sbase;
        for (int b = 255; b >= 0; b--) {
            if (cum + sbin[b] >= KPRE) { g_T16 = ch * 256 + b; g_S = cum; break; }
            cum += sbin[b];
        }
    }
}

// ---------------- K2: gather + (last block) 32-bit refine + compact key list ----------------
__global__ void gather_kernel(const float* __restrict__ obj, int N) {
    int i = blockIdx.x * 256 + threadIdx.x;
    if (i < N) {
        unsigned u = flipf(obj[i]);
        int hi = (int)(u >> 16);
        int T = g_T16;
        if (hi > T) {
            int p = atomicAdd(&g_cnt1, 1);
            if (p < 2048)
                g_cand[p] = ((unsigned long long)u << 32) |
                            (unsigned long long)(0xFFFFFFFFu - (unsigned)i);
        } else if (hi == T) {
            int p = atomicAdd(&g_cnt2, 1);
            if (p < 4096)
                g_cand2[p] = ((unsigned long long)u << 32) |
                             (unsigned long long)(0xFFFFFFFFu - (unsigned)i);
            atomicAdd(&g_hist2[u & 0xFFFFu], 1u);
        }
    }
    __syncthreads();
    __shared__ int lastf;
    if (threadIdx.x == 0) {
        __threadfence();
        lastf = (atomicAdd(&g_ctrg, 1u) == gridDim.x - 1);
    }
    __syncthreads();
    if (!lastf) return;

    __shared__ unsigned csum[256];
    __shared__ unsigned sbin[256];
    __shared__ int schunk;
    __shared__ unsigned sbase;
    __shared__ unsigned sT32;
    __shared__ int kc;
    int tid = threadIdx.x, w0 = tid >> 5, l = tid & 31;
    for (int t = w0; t < 256; t += 8) {
        unsigned s = 0;
        for (int b = l; b < 256; b += 32) s += g_hist2[t * 256 + b];
        #pragma unroll
        for (int o = 16; o; o >>= 1) s += __shfl_down_sync(0xffffffffu, s, o);
        if (!l) csum[t] = s;
    }
    __syncthreads();
    unsigned need = KPRE - g_S;
    if (tid == 0) {
        unsigned run = 0; int ch = 0; unsigned bs = 0;
        for (int t = 255; t >= 0; t--) {
            if (run + csum[t] >= need) { ch = t; bs = run; break; }
            run += csum[t];
        }
        schunk = ch; sbase = bs;
    }
    __syncthreads();
    int ch = schunk;
    if (w0 == 0) for (int b = l; b < 256; b += 32) sbin[b] = g_hist2[ch * 256 + b];
    __syncthreads();
    if (tid == 0) {
        unsigned cum = sbase;
        for (int b = 255; b >= 0; b--) {
            if (cum + sbin[b] >= need) {
                sT32 = ((unsigned)g_T16 << 16) | (unsigned)(ch * 256 + b);
                break;
            }
            cum += sbin[b];
        }
        kc = 0;
    }
    __syncthreads();
    unsigned T32 = sT32;
    int n1 = g_cnt1; if (n1 > 2048) n1 = 2048;
    for (int k = tid; k < n1; k += 256) g_keys[k] = g_cand[k];
    if (tid == 0) kc = n1;
    __syncthreads();
    int n2 = g_cnt2; if (n2 > 4096) n2 = 4096;
    for (int k = tid; k < n2; k += 256) {
        unsigned long long key = g_cand2[k];
        if ((unsigned)(key >> 32) >= T32) {
            int p = atomicAdd(&kc, 1);
            if (p < MAXKEY) g_keys[p] = key;
        }
    }
    __syncthreads();
    if (tid == 0) g_M = (kc < MAXKEY) ? kc : MAXKEY;
}

// ---------------- K3: pure fp16 transpose (exact R10-fast version) ----------------
__global__ void transpose_kernel(const float* __restrict__ f) {
    __shared__ float tile[64][65];
    int tid = threadIdx.x;
    int t  = blockIdx.x;                    // 0..2499
    int pb = t % PT, cb = t / PT;
    int p0 = pb * 64, c0 = cb * 64;
    #pragma unroll
    for (int r = 0; r < 4; r++) {
        int slot = r * 256 + tid;
        int ty = slot >> 4, tx = slot & 15;
        float4 v = *(const float4*)&f[(size_t)(c0 + ty) * HW + p0 + 4 * tx];
        tile[ty][4 * tx + 0] = v.x;
        tile[ty][4 * tx + 1] = v.y;
        tile[ty][4 * tx + 2] = v.z;
        tile[ty][4 * tx + 3] = v.w;
    }
    __syncthreads();
    #pragma unroll
    for (int r = 0; r < 4; r++) {
        int slot = r * 256 + tid;
        int pp = slot >> 4, k = slot & 15;
        __half2 h0 = __floats2half2_rn(tile[4 * k + 0][pp], tile[4 * k + 1][pp]);
        __half2 h1 = __floats2half2_rn(tile[4 * k + 2][pp], tile[4 * k + 3][pp]);
        uint2 pk;
        pk.x = *(unsigned*)&h0;
        pk.y = *(unsigned*)&h1;
        *(uint2*)&g_featT[(size_t)(p0 + pp) * CF + c0 + 4 * k] = pk;
    }
}

// ---------------- K4: mid = rank-v2 (blocks 0..159) | iou (160.., spin) + last-block NMS ----------------
union MidShared {
    unsigned long long sk[MAXKEY];       // 20 KB (rank branch)
    struct {
        float4 cb[4][64];                //  4 KB
        float  cA[4][64];                //  1 KB
        unsigned long long buf[2][64][33];   // 33.8 KB
        unsigned long long skeep[NWORD];
        unsigned long long part_sm[8];
        unsigned long long keptw;
    } iou;                               // ~39 KB
};

__global__ void mid_kernel(const float4* __restrict__ anchors,
                           const float4* __restrict__ deltas) {
    __shared__ MidShared u;
    __shared__ int s_stop;
    int tid = threadIdx.x;

    if (blockIdx.x < NRANKB) {
        // ======== rank v2: 16 threads per candidate ========
        int M = g_M;
        for (int j = tid; j < MAXKEY; j += 256)
            u.sk[j] = (j < M) ? g_keys[j] : 0ull;
        __syncthreads();
        int z = blockIdx.x * 256 + tid;
        if (z >= KPRE && z < NPAD) g_cand_boxes[z] = make_float4(0.f, 0.f, 0.f, 0.f);

        int cand = blockIdx.x * 16 + (tid >> 4);   // 0..2559
        int part = tid & 15;
        if (cand < M) {
            unsigned long long key = u.sk[cand];
            const ulonglong2* sk2 = (const ulonglong2*)u.sk;
            int rank = 0;
            #pragma unroll 8
            for (int j = part; j < MAXKEY / 2; j += 16) {
                ulonglong2 v = sk2[j];
                rank += (v.x > key);
                rank += (v.y > key);
            }
            #pragma unroll
            for (int o = 8; o; o >>= 1)
                rank += __shfl_down_sync(0xffffffffu, rank, o, 16);
            if (part == 0 && rank < KPRE) {
                unsigned i = ~(unsigned)(key & 0xFFFFFFFFull);
                float4 a = anchors[i];
                float4 d = deltas[i];
                float w  = a.z - a.x, h = a.w - a.y;
                float cx = a.x + 0.5f * w, cy = a.y + 0.5f * h;
                float dw = fminf(d.z, CLIPC), dh = fminf(d.w, CLIPC);
                float pcx = d.x * w + cx, pcy = d.y * h + cy;
                float pw  = expf(dw) * w, ph = expf(dh) * h;
                float bx1 = fminf(fmaxf(pcx - 0.5f * pw, 0.f), IMG);
                float by1 = fminf(fmaxf(pcy - 0.5f * ph, 0.f), IMG);
                float bx2 = fminf(fmaxf(pcx + 0.5f * pw, 0.f), IMG);
                float by2 = fminf(fmaxf(pcy + 0.5f * ph, 0.f), IMG);
                g_cand_boxes[rank] = make_float4(bx1, by1, bx2, by2);
            }
        }
        __syncthreads();
        if (tid == 0) { __threadfence(); atomicAdd(&g_rankdone, 1u); }
        return;
    }

    // ======== iou blocks: wait for rank, then 4 upper-tri tiles ========
    if (tid == 0) {
        while (*(volatile unsigned*)&g_rankdone < NRANKB) {}
        __threadfence();
    }
    __syncthreads();

    int sub = tid >> 6, tx = tid & 63;
    int t = (blockIdx.x - NRANKB) * 4 + sub;   // 0..527
    int ib = 0, off = 0;
    for (int r = 0; r < 32; r++) {
        int cnt = 32 - r;
        if (t < off + cnt) { ib = r; break; }
        off += cnt;
    }
    int by = ib + (t - off);

    float4 bb = g_cand_boxes[by * 64 + tx];
    u.iou.cb[sub][tx] = bb;
    u.iou.cA[sub][tx] = 0.7f * (bb.z - bb.x) * (bb.w - bb.y);
    __syncthreads();

    int i = ib * 64 + tx;
    float4 a = g_cand_boxes[i];
    float c0 = 0.7f * ((a.z - a.x) * (a.w - a.y) + 1e-6f);
    unsigned long long bits = 0ull;
    #pragma unroll 8
    for (int jj = 0; jj < 64; jj++) {
        float4 b = u.iou.cb[sub][jj];
        float lx = fmaxf(a.x, b.x), ly = fmaxf(a.y, b.y);
        float rx = fminf(a.z, b.z), ry = fminf(a.w, b.w);
        float wx = fmaxf(rx - lx, 0.f), wy = fmaxf(ry - ly, 0.f);
        float inter = wx * wy;
        unsigned long long p = (fmaf(1.7f, inter, -(c0 + u.iou.cA[sub][jj])) > 0.f);
        bits |= p << jj;
    }
    if (by == ib) bits &= (tx == 63) ? 0ull : (~0ull << (tx + 1));
    g_mask[(size_t)i * NWORD + by] = bits;

    __syncthreads();
    __shared__ int lastf;
    if (tid == 0) {
        __threadfence();
        lastf = (atomicAdd(&g_ctri, 1u) == NIOU - 1);
    }
    __syncthreads();
    if (!lastf) return;

    // ======== parallel NMS (cluster-skip greedy + distributed accumulation) ========
    int lane = tid & 31;
    int wrp  = tid >> 5;
    unsigned long long part_reg = 0ull;
    if (tid == 0) s_stop = 0;
    if (tid < 8) u.iou.part_sm[tid] = 0ull;
    #pragma unroll
    for (int k = 0; k < 8; k++) {
        int idx = tid + k * 256;
        u.iou.buf[0][idx >> 5][idx & 31] = g_mask[(size_t)(idx >> 5) * NWORD + (idx & 31)];
    }
    __syncthreads();

    int kept_total = 0;
    int cend = NWORD;
    for (int c = 0; c < NWORD; c++) {
        int par = c & 1;
        if (c + 1 < NWORD) {
            int base1 = (c + 1) * 64;
            #pragma unroll
            for (int k = 0; k < 8; k++) {
                int idx = tid + k * 256;
                u.iou.buf[par ^ 1][idx >> 5][idx & 31] =
                    g_mask[(size_t)(base1 + (idx >> 5)) * NWORD + (idx & 31)];
            }
        }
        if (wrp == 0) {
            unsigned long long rem = (lane < 8) ? u.iou.part_sm[lane] : 0ull;
            rem |= __shfl_xor_sync(0xffffffffu, rem, 4);
            rem |= __shfl_xor_sync(0xffffffffu, rem, 2);
            rem |= __shfl_xor_sync(0xffffffffu, rem, 1);
            rem  = __shfl_sync(0xffffffffu, rem, 0);
            unsigned long long keepmask = (c == NWORD - 1) ? 0xFFFFull : ~0ull;
            unsigned long long td = ~rem & keepmask;
            unsigned long long sd_lo = u.iou.buf[par][lane][c];
            unsigned long long sd_hi = u.iou.buf[par][lane + 32][c];
            unsigned long long kept = 0ull;
            while (td) {
                unsigned long long row = 0ull;
                if ((td >> lane) & 1ull)        row  = sd_lo;
                if ((td >> (lane + 32)) & 1ull) row |= sd_hi;
                #pragma unroll
                for (int o = 16; o; o >>= 1)
                    row |= __shfl_xor_sync(0xffffffffu, row, o);
                unsigned long long tgt = row & td;
                if (tgt == 0ull) { kept |= td; break; }
                int s = __ffsll((long long)tgt) - 1;
                unsigned long long low = td & ((1ull << s) - 1ull);
                kept |= low;
                unsigned long long row2 = 0ull;
                if ((low >> lane) & 1ull)        row2  = sd_lo;
                if ((low >> (lane + 32)) & 1ull) row2 |= sd_hi;
                #pragma unroll
                for (int o = 16; o; o >>= 1)
                    row2 |= __shfl_xor_sync(0xffffffffu, row2, o);
                td &= ~(low | row2);
            }
            if (lane == 0) {
                u.iou.skeep[c] = kept;
                u.iou.keptw    = kept;
                kept_total += __popcll(kept);
                if (kept_total >= KPOST) s_stop = 1;
            }
        }
        __syncthreads();
        if (s_stop) { cend = c + 1; break; }
        unsigned long long kw = u.iou.keptw;
        int cnt2 = 0;
        while (kw) {
            int b = __ffsll((long long)kw) - 1;
            if ((cnt2 & 7) == wrp) part_reg |= u.iou.buf[par][b][lane];
            kw &= (kw - 1);
            cnt2++;
        }
        if (lane == c + 1) u.iou.part_sm[wrp] = part_reg;
        __syncthreads();
    }

    // ---- compaction (warp 0) ----
    if (wrp != 0) return;
    for (int cc = cend + lane; cc < NWORD; cc += 32) u.iou.skeep[cc] = 0ull;
    __syncwarp();
    for (int s = lane; s < KPOST; s += 32) g_valid[s] = 0;
    __syncwarp();
    unsigned long long kw = u.iou.skeep[lane];
    int cnt = __popcll(kw);
    int pre = cnt;
    #pragma unroll
    for (int o = 1; o < 32; o <<= 1) {
        int n = __shfl_up_sync(0xffffffffu, pre, o);
        if (lane >= o) pre += n;
    }
    pre -= cnt;
    unsigned long long w2 = kw; int r = 0;
    while (w2) {
        int b = __ffsll((long long)w2) - 1;
        int s = pre + r;
        if (s < KPOST) {
            g_valid[s] = 1;
            g_fboxes[s] = g_cand_boxes[lane * 64 + b];
        }
        w2 &= (w2 - 1); r++;
    }
}

// ---------------- K5: ROIAlign + self-clean for next graph replay ----------------
#define SPAD   65
#define SOUT_F 3188                             // 49*65=3185, padded (16B align)
#define ROI_SMEM (SOUT_F*4 + 196*16 + 196*16)   // ~19.0 KB

__global__ void roi_kernel(float* __restrict__ out) {
    extern __shared__ float sm[];
    float*  s_out = sm;
    int4*   s_off = (int4*)(sm + SOUT_F);
    float4* s_w   = (float4*)(s_off + 196);

    int slot = blockIdx.x >> 2;
    int quar = blockIdx.x & 3;
    int tid  = threadIdx.x;
    float* o = out + (size_t)slot * (CF * 49) + quar * (64 * 49);

    // ---- self-clean scratch for the NEXT replay ----
    if (tid < 16) {
        int idx = blockIdx.x * 16 + tid;        // 2048*16 = 32768 uint4 exactly
        uint4 z = make_uint4(0, 0, 0, 0);
        if (idx < 16384) ((uint4*)g_hist)[idx] = z;
        else             ((uint4*)g_hist2)[idx - 16384] = z;
    }
    if (blockIdx.x == 0 && tid == 0) {
        g_cnt1 = 0; g_cnt2 = 0; g_ctrd = 0; g_ctrg = 0; g_ctri = 0;
        g_rankdone = 0;
    }

    if (!g_valid[slot]) {
        for (int g = tid; g < 64 * 49; g += 256) o[g] = 0.0f;
        return;
    }
    float4 b = g_fboxes[slot];
    if (tid < 196) {
        float x1 = b.x * SCALE, y1 = b.y * SCALE;
        float x2 = b.z * SCALE, y2 = b.w * SCALE;
        float rw = fmaxf(x2 - x1, 1.0f), rh = fmaxf(y2 - y1, 1.0f);
        int sy = tid / 14, sx = tid % 14;
        float yv = y1 + ((float)sy + 0.5f) * (rh / 14.0f);
        float xv = x1 + ((float)sx + 0.5f) * (rw / 14.0f);
        yv = fminf(fmaxf(yv, 0.0f), (float)(HF - 1));
        xv = fminf(fmaxf(xv, 0.0f), (float)(WF - 1));
        int y0 = (int)floorf(yv), x0 = (int)floorf(xv);
        int y1i = min(y0 + 1, HF - 1), x1i = min(x0 + 1, WF - 1);
        float ly = yv - (float)y0, lx = xv - (float)x0;
        s_off[tid] = make_int4((y0 * WF + x0) * CF,  (y0 * WF + x1i) * CF,
                               (y1i * WF + x0) * CF, (y1i * WF + x1i) * CF);
        s_w[tid] = make_float4((1.f - ly) * (1.f - lx), (1.f - ly) * lx,
                               ly * (1.f - lx),          ly * lx);
    }
    __syncthreads();

    int cg = tid & 15;
    int pq = tid >> 4;
    int cbase = quar * 64 + 4 * cg;

    for (int p = pq; p < 49; p += 16) {
        int oy = p / 7, ox = p % 7;
        float ax = 0.f, ay = 0.f, az = 0.f, aw = 0.f;
        #pragma unroll
        for (int a = 0; a < 2; a++) {
            #pragma unroll
            for (int bbq = 0; bbq < 2; bbq++) {
                int s = (2 * oy + a) * 14 + (2 * ox + bbq);
                int4   of = s_off[s];
                float4 wv = s_w[s];
                uint2 r00 = *(const uint2*)&g_featT[(size_t)(unsigned)of.x + cbase];
                uint2 r01 = *(const uint2*)&g_featT[(size_t)(unsigned)of.y + cbase];
                uint2 r10 = *(const uint2*)&g_featT[(size_t)(unsigned)of.z + cbase];
                uint2 r11 = *(const uint2*)&g_featT[(size_t)(unsigned)of.w + cbase];
                float2 a0 = __half22float2(*(__half2*)&r00.x);
                float2 a1 = __half22float2(*(__half2*)&r00.y);
                float2 b0 = __half22float2(*(__half2*)&r01.x);
                float2 b1 = __half22float2(*(__half2*)&r01.y);
                float2 c0 = __half22float2(*(__half2*)&r10.x);
                float2 c1 = __half22float2(*(__half2*)&r10.y);
                float2 d0 = __half22float2(*(__half2*)&r11.x);
                float2 d1 = __half22float2(*(__half2*)&r11.y);
                ax += wv.x * a0.x + wv.y * b0.x + wv.z * c0.x + wv.w * d0.x;
                ay += wv.x * a0.y + wv.y * b0.y + wv.z * c0.y + wv.w * d0.y;
                az += wv.x * a1.x + wv.y * b1.x + wv.z * c1.x + wv.w * d1.x;
                aw += wv.x * a1.y + wv.y * b1.y + wv.z * c1.y + wv.w * d1.y;
            }
        }
        int base = p * SPAD + 4 * cg;
        s_out[base + 0] = ax * 0.25f;
        s_out[base + 1] = ay * 0.25f;
        s_out[base + 2] = az * 0.25f;
        s_out[base + 3] = aw * 0.25f;
    }
    __syncthreads();

    for (int g = tid; g < 64 * 49; g += 256) {
        int cc = g / 49;
        int p  = g - 49 * cc;
        o[g] = s_out[p * SPAD + cc];
    }
}

// ---------------- launcher ----------------
extern "C" void kernel_launch(void* const* d_in, const int* in_sizes, int n_in,
                              void* d_out, int out_size) {
    const float*  feature = (const float*)d_in[0];
    const float*  obj     = (const float*)d_in[1];
    const float4* deltas  = (const float4*)d_in[2];
    const float4* anchors = (const float4*)d_in[3];
    float* out = (float*)d_out;
    int N = in_sizes[1];
    int nbH = (N + 255) / 256;

    cudaFuncSetAttribute(roi_kernel, cudaFuncAttributeMaxDynamicSharedMemorySize, ROI_SMEM);

    hist_kernel<<<nbH, 256>>>(obj, N);
    gather_kernel<<<nbH, 256>>>(obj, N);
    transpose_kernel<<<TTOT, 256>>>(feature);
    mid_kernel<<<NRANKB + NIOU, 256>>>(anchors, deltas);
    roi_kernel<<<4 * KPOST, 256, ROI_SMEM>>>(out);
}